// round 1
// baseline (speedup 1.0000x reference)
#include <cuda_runtime.h>
#include <math.h>

// Problem constants
#define BB 64      // batch
#define TT 512     // time
#define EE 512     // embed
#define HH 512     // hidden per direction
#define G4 2048    // 4*H
#define KK 23      // tags
#define START_TAG 1
#define END_TAG 2
#define NEGV -10000.0f

// ---------------- scratch (device globals; no allocation) ----------------
// xg[dir][(b*T+t)*2048 + gate*512 + j]  : input-projection + bias
__device__ float g_xg[2][67108864];          // 2 * 32768 * 2048 floats (536 MB)
// hs[dir][(t*512 + j)*64 + b]           : full hidden sequence, [t][j][b]
__device__ float g_hs[2][16777216];          // 134 MB
// double-buffered recurrent state, layout [j*64 + b]
__device__ float g_hbuf[2][2][HH * BB];
__device__ float g_c[2][HH * BB];
// emissions feats[(b*T+t)*23 + k]
__device__ float g_feats[BB * TT * KK];

// ---------------- init: zero recurrent state ----------------
__global__ void init_state_kernel() {
    int idx = blockIdx.x * blockDim.x + threadIdx.x;
    int n1 = 2 * 2 * HH * BB;
    int n2 = 2 * HH * BB;
    for (int i = idx; i < n1; i += gridDim.x * blockDim.x)
        ((float*)g_hbuf)[i] = 0.0f;
    for (int i = idx; i < n2; i += gridDim.x * blockDim.x)
        ((float*)g_c)[i] = 0.0f;
}

// ---------------- input GEMM: C[m,n] = sum_k A[m,k]*W[n,k] + bias[n] ------
// A: [32768, 512] row-major, W: [2048, 512] row-major, C: g_xg[dir]
// tile: BM=128, BN=64, BK=16; 256 threads; thread tile 8x4
__global__ void xgemm_kernel(const float* __restrict__ A,
                             const float* __restrict__ Wf,
                             const float* __restrict__ Wb,
                             const float* __restrict__ bf,
                             const float* __restrict__ bb) {
    const int dir = blockIdx.z;
    const float* __restrict__ W = dir ? Wb : Wf;
    const float* __restrict__ bias = dir ? bb : bf;
    float* __restrict__ C = g_xg[dir];

    __shared__ float As[16][128];
    __shared__ float Bs[16][64];

    const int tid = threadIdx.x;
    const int tx = tid & 15;   // n: 16 groups of 4
    const int ty = tid >> 4;   // m: 16 groups of 8
    const int m0 = blockIdx.y * 128;
    const int n0 = blockIdx.x * 64;

    float acc[8][4];
#pragma unroll
    for (int i = 0; i < 8; i++)
#pragma unroll
        for (int j = 0; j < 4; j++) acc[i][j] = 0.0f;

    for (int kt = 0; kt < EE; kt += 16) {
        // load A tile 128x16 (512 float4, 2 per thread)
#pragma unroll
        for (int i = 0; i < 2; i++) {
            int idx = tid + i * 256;
            int row = idx >> 2;
            int qc  = idx & 3;
            float4 v = *(const float4*)(A + (size_t)(m0 + row) * EE + kt + qc * 4);
            As[qc * 4 + 0][row] = v.x;
            As[qc * 4 + 1][row] = v.y;
            As[qc * 4 + 2][row] = v.z;
            As[qc * 4 + 3][row] = v.w;
        }
        // load W tile 64x16 (256 float4, 1 per thread)
        {
            int row = tid >> 2;
            int qc  = tid & 3;
            float4 v = *(const float4*)(W + (size_t)(n0 + row) * EE + kt + qc * 4);
            Bs[qc * 4 + 0][row] = v.x;
            Bs[qc * 4 + 1][row] = v.y;
            Bs[qc * 4 + 2][row] = v.z;
            Bs[qc * 4 + 3][row] = v.w;
        }
        __syncthreads();
#pragma unroll
        for (int k = 0; k < 16; k++) {
            float4 a0 = *(const float4*)&As[k][ty * 8];
            float4 a1 = *(const float4*)&As[k][ty * 8 + 4];
            float4 b4 = *(const float4*)&Bs[k][tx * 4];
            float av[8] = {a0.x, a0.y, a0.z, a0.w, a1.x, a1.y, a1.z, a1.w};
            float bv[4] = {b4.x, b4.y, b4.z, b4.w};
#pragma unroll
            for (int i = 0; i < 8; i++)
#pragma unroll
                for (int j = 0; j < 4; j++)
                    acc[i][j] = fmaf(av[i], bv[j], acc[i][j]);
        }
        __syncthreads();
    }
    // epilogue with bias
    float4 bias4 = *(const float4*)(bias + n0 + tx * 4);
#pragma unroll
    for (int i = 0; i < 8; i++) {
        int m = m0 + ty * 8 + i;
        float4 o;
        o.x = acc[i][0] + bias4.x;
        o.y = acc[i][1] + bias4.y;
        o.z = acc[i][2] + bias4.z;
        o.w = acc[i][3] + bias4.w;
        *(float4*)(C + (size_t)m * G4 + n0 + tx * 4) = o;
    }
}

// ---------------- LSTM recurrent step (both directions fused) -------------
// grid: (32 unit-blocks of 16 units, 2 batch-halves, 2 dirs), 256 threads
__global__ void lstm_step_kernel(int s,
                                 const float* __restrict__ Whh_f,
                                 const float* __restrict__ Whh_b) {
    const int dir   = blockIdx.z;
    const int bhalf = blockIdx.y;
    const int ublk  = blockIdx.x;
    const float* __restrict__ Whh = dir ? Whh_b : Whh_f;
    const int t_d = dir ? (TT - 1 - s) : s;

    extern __shared__ float hs[];  // [512][32] = 64 KB
    const float* __restrict__ hprev = g_hbuf[dir][s & 1];
    float* __restrict__ hnext = g_hbuf[dir][(s + 1) & 1];

    const int tid  = threadIdx.x;
    const int lane = tid & 31;
    const int w    = tid >> 5;
    const int b    = bhalf * 32 + lane;

    // stage h slice [512][32] into smem (coalesced: [k][b] layout in gmem)
    for (int idx = tid; idx < HH * 32; idx += 256) {
        int k  = idx >> 5;
        int bb = idx & 31;
        hs[idx] = hprev[k * BB + bhalf * 32 + bb];
    }
    __syncthreads();

#pragma unroll
    for (int uu = 0; uu < 2; uu++) {
        const int j = ublk * 16 + w * 2 + uu;
        const float4* __restrict__ wi = (const float4*)(Whh + (size_t)(0 * HH + j) * HH);
        const float4* __restrict__ wf = (const float4*)(Whh + (size_t)(1 * HH + j) * HH);
        const float4* __restrict__ wg = (const float4*)(Whh + (size_t)(2 * HH + j) * HH);
        const float4* __restrict__ wo = (const float4*)(Whh + (size_t)(3 * HH + j) * HH);
        float ai = 0.f, af = 0.f, ag = 0.f, ao = 0.f;
#pragma unroll 4
        for (int kc = 0; kc < HH / 4; kc++) {
            float4 vi = __ldg(wi + kc);
            float4 vf = __ldg(wf + kc);
            float4 vg = __ldg(wg + kc);
            float4 vo = __ldg(wo + kc);
            float h0 = hs[(kc * 4 + 0) * 32 + lane];
            float h1 = hs[(kc * 4 + 1) * 32 + lane];
            float h2 = hs[(kc * 4 + 2) * 32 + lane];
            float h3 = hs[(kc * 4 + 3) * 32 + lane];
            ai = fmaf(vi.x, h0, ai); ai = fmaf(vi.y, h1, ai);
            ai = fmaf(vi.z, h2, ai); ai = fmaf(vi.w, h3, ai);
            af = fmaf(vf.x, h0, af); af = fmaf(vf.y, h1, af);
            af = fmaf(vf.z, h2, af); af = fmaf(vf.w, h3, af);
            ag = fmaf(vg.x, h0, ag); ag = fmaf(vg.y, h1, ag);
            ag = fmaf(vg.z, h2, ag); ag = fmaf(vg.w, h3, ag);
            ao = fmaf(vo.x, h0, ao); ao = fmaf(vo.y, h1, ao);
            ao = fmaf(vo.z, h2, ao); ao = fmaf(vo.w, h3, ao);
        }
        const size_t base = ((size_t)b * TT + t_d) * G4 + j;
        const float* __restrict__ xg = g_xg[dir];
        ai += xg[base];
        af += xg[base + HH];
        ag += xg[base + 2 * HH];
        ao += xg[base + 3 * HH];

        float ig = 1.0f / (1.0f + expf(-ai));
        float fg = 1.0f / (1.0f + expf(-af));
        float gg = tanhf(ag);
        float og = 1.0f / (1.0f + expf(-ao));

        const int sidx = j * BB + b;
        float cprev = g_c[dir][sidx];
        float cnew  = fg * cprev + ig * gg;
        float hv    = og * tanhf(cnew);
        g_c[dir][sidx] = cnew;
        hnext[sidx]    = hv;
        g_hs[dir][((size_t)t_d * HH + j) * BB + b] = hv;
    }
}

// ---------------- emissions: feats = [h_f, h_b] @ W_h2t^T + b_h2t ---------
// grid 128 blocks x 256 threads; warp w: t = bx*4 + (w>>1), bhalf = w&1
__global__ void feats_kernel(const float* __restrict__ Wh2t,
                             const float* __restrict__ bh2t) {
    extern __shared__ float Ws[];  // [23][1024]
    const int tid = threadIdx.x;
    for (int i = tid; i < KK * 1024; i += 256) Ws[i] = Wh2t[i];
    __syncthreads();

    const int w    = tid >> 5;
    const int lane = tid & 31;
    const int t    = blockIdx.x * 4 + (w >> 1);
    const int b    = (w & 1) * 32 + lane;

    float acc[KK];
#pragma unroll
    for (int k = 0; k < KK; k++) acc[k] = __ldg(bh2t + k);

    const float* __restrict__ hf = g_hs[0] + (size_t)t * HH * BB;
    for (int j = 0; j < HH; j++) {
        float hv = hf[j * BB + b];
#pragma unroll
        for (int k = 0; k < KK; k++)
            acc[k] = fmaf(hv, Ws[k * 1024 + j], acc[k]);
    }
    const float* __restrict__ hb = g_hs[1] + (size_t)t * HH * BB;
    for (int j = 0; j < HH; j++) {
        float hv = hb[j * BB + b];
#pragma unroll
        for (int k = 0; k < KK; k++)
            acc[k] = fmaf(hv, Ws[k * 1024 + HH + j], acc[k]);
    }
#pragma unroll
    for (int k = 0; k < KK; k++)
        g_feats[((size_t)b * TT + t) * KK + k] = acc[k];
}

// ---------------- Viterbi: one warp per batch element ---------------------
__global__ void viterbi_kernel(const float* __restrict__ trans,
                               const int* __restrict__ seq_len,
                               float* __restrict__ out) {
    const int b    = blockIdx.x;
    const int lane = threadIdx.x;
    __shared__ unsigned char bp[TT][24];

    const int L = seq_len[b];
    const bool active = lane < KK;

    float tr[KK];
#pragma unroll
    for (int p = 0; p < KK; p++)
        tr[p] = active ? trans[lane * KK + p] : -3.0e38f;

    float fv = (lane == START_TAG) ? 0.0f : NEGV;  // matches init for all lanes<K
    const float* __restrict__ fb = g_feats + (size_t)b * TT * KK;

    for (int t = 0; t < TT; t++) {
        float ft = active ? fb[t * KK + lane] : 0.0f;
        float best = -3.4e38f;
        int arg = 0;
#pragma unroll
        for (int p = 0; p < KK; p++) {
            float v = __shfl_sync(0xffffffffu, fv, p) + tr[p];
            if (v > best) { best = v; arg = p; }  // strict > => first max (jnp.argmax)
        }
        const bool m = (t < L);
        if (m) fv = best + ft;
        if (active) bp[t][lane] = m ? (unsigned char)arg : (unsigned char)lane;
    }

    float term = active ? (fv + trans[END_TAG * KK + lane]) : -3.4e38f;
    float bestv = -3.4e38f;
    int btag = 0;
#pragma unroll
    for (int p = 0; p < KK; p++) {
        float v = __shfl_sync(0xffffffffu, term, p);
        if (v > bestv) { bestv = v; btag = p; }
    }

    if (lane == 0) {
        out[b] = bestv;
        int tag = btag;
        out[BB + (size_t)b * TT + (TT - 1)] = (float)tag;
        for (int t = TT - 1; t >= 1; t--) {
            tag = bp[t][tag];
            out[BB + (size_t)b * TT + (t - 1)] = (float)tag;
        }
    }
}

// ---------------- launch -------------------------------------------------
extern "C" void kernel_launch(void* const* d_in, const int* in_sizes, int n_in,
                              void* d_out, int out_size) {
    const float* texts  = (const float*)d_in[0];
    const int*   seqlen = (const int*)d_in[1];
    const float* Wih_f  = (const float*)d_in[2];
    const float* Whh_f  = (const float*)d_in[3];
    const float* b_f    = (const float*)d_in[4];
    const float* Wih_b  = (const float*)d_in[5];
    const float* Whh_b  = (const float*)d_in[6];
    const float* b_b    = (const float*)d_in[7];
    const float* W_h2t  = (const float*)d_in[8];
    const float* b_h2t  = (const float*)d_in[9];
    const float* trans  = (const float*)d_in[10];
    float* out = (float*)d_out;

    cudaFuncSetAttribute(lstm_step_kernel,
                         cudaFuncAttributeMaxDynamicSharedMemorySize, 64 * 1024);
    cudaFuncSetAttribute(feats_kernel,
                         cudaFuncAttributeMaxDynamicSharedMemorySize, KK * 1024 * 4);

    init_state_kernel<<<128, 256>>>();
    xgemm_kernel<<<dim3(G4 / 64, (BB * TT) / 128, 2), 256>>>(texts, Wih_f, Wih_b, b_f, b_b);
    for (int s = 0; s < TT; s++)
        lstm_step_kernel<<<dim3(32, 2, 2), 256, 64 * 1024>>>(s, Whh_f, Whh_b);
    feats_kernel<<<128, 256, KK * 1024 * 4>>>(W_h2t, b_h2t);
    viterbi_kernel<<<BB, 32>>>(trans, seqlen, out);
}

// round 2
// speedup vs baseline: 1.9436x; 1.9436x over previous
#include <cuda_runtime.h>
#include <math.h>

// Problem constants
#define BB 64      // batch
#define TT 512     // time
#define EE 512     // embed
#define HH 512     // hidden per direction
#define G4 2048    // 4*H
#define KK 23      // tags
#define START_TAG 1
#define END_TAG 2
#define NEGV -10000.0f
#define NBLK 256   // persistent grid size

// ---------------- scratch (device globals; no allocation) ----------------
__device__ float g_xg[2][67108864];          // [dir][(b*T+t)*2048 + g*512 + u]
__device__ float g_hs[2][16777216];          // [dir][t*512*64 + u*64 + b]
__device__ float g_zero[HH * BB];            // stays zero (h_{-1})
__device__ float g_feats[BB * TT * KK];
__device__ unsigned int g_bar;

__global__ void init_kernel() {
    int idx = blockIdx.x * blockDim.x + threadIdx.x;
    for (int i = idx; i < HH * BB; i += gridDim.x * blockDim.x) g_zero[i] = 0.0f;
    if (idx == 0) g_bar = 0u;
}

// ---------------- input GEMM: C[m,n] = sum_k A[m,k]*W[n,k] + bias[n] ------
// A: [32768,512], W: [2048,512]. Tile 128x128xBK8, 256 thr, 8x8 micro (4+64 split)
__global__ __launch_bounds__(256, 2)
void xgemm_kernel(const float* __restrict__ A,
                  const float* __restrict__ Wf,
                  const float* __restrict__ Wb,
                  const float* __restrict__ bf,
                  const float* __restrict__ bb) {
    const int dir = blockIdx.z;
    const float* __restrict__ W = dir ? Wb : Wf;
    const float* __restrict__ bias = dir ? bb : bf;
    float* __restrict__ C = g_xg[dir];

    __shared__ __align__(16) float As[8][128];
    __shared__ __align__(16) float Bs[8][128];

    const int tid = threadIdx.x;
    const int m0 = blockIdx.y * 128;
    const int n0 = blockIdx.x * 128;
    const int lrow = tid >> 1;          // 0..127
    const int lkq  = (tid & 1) * 4;     // 0 or 4
    const int tx = (tid & 15) * 4;      // n frag base (also +64)
    const int ty = (tid >> 4) * 4;      // m frag base (also +64)

    float acc[8][8];
#pragma unroll
    for (int i = 0; i < 8; i++)
#pragma unroll
        for (int j = 0; j < 8; j++) acc[i][j] = 0.0f;

    for (int kt = 0; kt < EE; kt += 8) {
        float4 av = *(const float4*)(A + (size_t)(m0 + lrow) * EE + kt + lkq);
        float4 bv = *(const float4*)(W + (size_t)(n0 + lrow) * EE + kt + lkq);
        As[lkq + 0][lrow] = av.x; As[lkq + 1][lrow] = av.y;
        As[lkq + 2][lrow] = av.z; As[lkq + 3][lrow] = av.w;
        Bs[lkq + 0][lrow] = bv.x; Bs[lkq + 1][lrow] = bv.y;
        Bs[lkq + 2][lrow] = bv.z; Bs[lkq + 3][lrow] = bv.w;
        __syncthreads();
#pragma unroll
        for (int k = 0; k < 8; k++) {
            float4 a0 = *(const float4*)&As[k][ty];
            float4 a1 = *(const float4*)&As[k][ty + 64];
            float4 b0 = *(const float4*)&Bs[k][tx];
            float4 b1 = *(const float4*)&Bs[k][tx + 64];
            float am[8] = {a0.x, a0.y, a0.z, a0.w, a1.x, a1.y, a1.z, a1.w};
            float bn[8] = {b0.x, b0.y, b0.z, b0.w, b1.x, b1.y, b1.z, b1.w};
#pragma unroll
            for (int i = 0; i < 8; i++)
#pragma unroll
                for (int j = 0; j < 8; j++)
                    acc[i][j] = fmaf(am[i], bn[j], acc[i][j]);
        }
        __syncthreads();
    }
    // epilogue + bias
    float4 bia0 = *(const float4*)(bias + n0 + tx);
    float4 bia1 = *(const float4*)(bias + n0 + tx + 64);
    float bn[8] = {bia0.x, bia0.y, bia0.z, bia0.w, bia1.x, bia1.y, bia1.z, bia1.w};
#pragma unroll
    for (int i = 0; i < 8; i++) {
        int m = m0 + ((i < 4) ? (ty + i) : (ty + 64 + i - 4));
        float4 o0, o1;
        o0.x = acc[i][0] + bn[0]; o0.y = acc[i][1] + bn[1];
        o0.z = acc[i][2] + bn[2]; o0.w = acc[i][3] + bn[3];
        o1.x = acc[i][4] + bn[4]; o1.y = acc[i][5] + bn[5];
        o1.z = acc[i][6] + bn[6]; o1.w = acc[i][7] + bn[7];
        *(float4*)(C + (size_t)m * G4 + n0 + tx)      = o0;
        *(float4*)(C + (size_t)m * G4 + n0 + tx + 64) = o1;
    }
}

// ---------------- persistent bidirectional LSTM ---------------------------
// 256 blocks x 128 threads. block: dir = blk>>7, 4 hidden units (ublk*4..+3).
// warp = one unit; thread = lane -> 2 batches (b0=lane*2), all 4 gates.
// Whh slice (4 units x 4 gates x 512) cached in smem once for all 512 steps.
__device__ __forceinline__ float sigf(float x) {
    return 1.0f / (1.0f + __expf(-x));
}
__device__ __forceinline__ float tanhfast(float x) {
    return 1.0f - 2.0f / (__expf(2.0f * x) + 1.0f);
}

__global__ __launch_bounds__(128, 2)
void lstm_persistent(const float* __restrict__ Whh_f,
                     const float* __restrict__ Whh_b) {
    const int blk  = blockIdx.x;
    const int dir  = blk >> 7;
    const int ublk = blk & 127;
    const float* __restrict__ Whh = dir ? Whh_b : Whh_f;

    __shared__ __align__(16) float wsm[4][4][HH];   // [u_local][gate][k] 32KB

    const int tid  = threadIdx.x;
    const int warp = tid >> 5;
    const int lane = tid & 31;

    // load weight slice once
    for (int idx = tid; idx < 4 * 4 * HH; idx += 128) {
        int u = idx >> 11;
        int g = (idx >> 9) & 3;
        int k = idx & 511;
        wsm[u][g][k] = Whh[(size_t)(g * HH + ublk * 4 + u) * HH + k];
    }
    __syncthreads();

    const int u_glob = ublk * 4 + warp;
    const int b0 = lane * 2;
    const float* __restrict__ xg = g_xg[dir];
    float* __restrict__ hs_base = g_hs[dir];

    float c0 = 0.0f, c1 = 0.0f;

    for (int s = 0; s < TT; s++) {
        const int t = dir ? (TT - 1 - s) : s;
        const float* __restrict__ hprev =
            (s == 0) ? g_zero : (hs_base + (size_t)(dir ? t + 1 : t - 1) * HH * BB);

        float ai0 = 0.f, af0 = 0.f, ag0 = 0.f, ao0 = 0.f;
        float ai1 = 0.f, af1 = 0.f, ag1 = 0.f, ao1 = 0.f;

#pragma unroll 2
        for (int k = 0; k < HH; k += 4) {
            const float4 wi = *(const float4*)&wsm[warp][0][k];
            const float4 wf = *(const float4*)&wsm[warp][1][k];
            const float4 wg = *(const float4*)&wsm[warp][2][k];
            const float4 wo = *(const float4*)&wsm[warp][3][k];
            const float2 h0 = *(const float2*)&hprev[(k + 0) * BB + b0];
            const float2 h1 = *(const float2*)&hprev[(k + 1) * BB + b0];
            const float2 h2 = *(const float2*)&hprev[(k + 2) * BB + b0];
            const float2 h3 = *(const float2*)&hprev[(k + 3) * BB + b0];
            ai0 = fmaf(wi.x, h0.x, ai0); ai1 = fmaf(wi.x, h0.y, ai1);
            af0 = fmaf(wf.x, h0.x, af0); af1 = fmaf(wf.x, h0.y, af1);
            ag0 = fmaf(wg.x, h0.x, ag0); ag1 = fmaf(wg.x, h0.y, ag1);
            ao0 = fmaf(wo.x, h0.x, ao0); ao1 = fmaf(wo.x, h0.y, ao1);
            ai0 = fmaf(wi.y, h1.x, ai0); ai1 = fmaf(wi.y, h1.y, ai1);
            af0 = fmaf(wf.y, h1.x, af0); af1 = fmaf(wf.y, h1.y, af1);
            ag0 = fmaf(wg.y, h1.x, ag0); ag1 = fmaf(wg.y, h1.y, ag1);
            ao0 = fmaf(wo.y, h1.x, ao0); ao1 = fmaf(wo.y, h1.y, ao1);
            ai0 = fmaf(wi.z, h2.x, ai0); ai1 = fmaf(wi.z, h2.y, ai1);
            af0 = fmaf(wf.z, h2.x, af0); af1 = fmaf(wf.z, h2.y, af1);
            ag0 = fmaf(wg.z, h2.x, ag0); ag1 = fmaf(wg.z, h2.y, ag1);
            ao0 = fmaf(wo.z, h2.x, ao0); ao1 = fmaf(wo.z, h2.y, ao1);
            ai0 = fmaf(wi.w, h3.x, ai0); ai1 = fmaf(wi.w, h3.y, ai1);
            af0 = fmaf(wf.w, h3.x, af0); af1 = fmaf(wf.w, h3.y, af1);
            ag0 = fmaf(wg.w, h3.x, ag0); ag1 = fmaf(wg.w, h3.y, ag1);
            ao0 = fmaf(wo.w, h3.x, ao0); ao1 = fmaf(wo.w, h3.y, ao1);
        }

        // add input projection (+bias, already folded)
        const size_t xb0 = ((size_t)b0 * TT + t) * G4 + u_glob;
        const size_t xb1 = xb0 + (size_t)TT * G4;
        ai0 += xg[xb0];            ai1 += xg[xb1];
        af0 += xg[xb0 + HH];       af1 += xg[xb1 + HH];
        ag0 += xg[xb0 + 2 * HH];   ag1 += xg[xb1 + 2 * HH];
        ao0 += xg[xb0 + 3 * HH];   ao1 += xg[xb1 + 3 * HH];

        const float i0 = sigf(ai0), f0 = sigf(af0), gg0 = tanhfast(ag0), o0 = sigf(ao0);
        const float i1 = sigf(ai1), f1 = sigf(af1), gg1 = tanhfast(ag1), o1 = sigf(ao1);
        c0 = f0 * c0 + i0 * gg0;
        c1 = f1 * c1 + i1 * gg1;
        float2 hv;
        hv.x = o0 * tanhfast(c0);
        hv.y = o1 * tanhfast(c1);
        *(float2*)&hs_base[(size_t)t * HH * BB + u_glob * BB + b0] = hv;

        // global barrier (skip after last step)
        if (s != TT - 1) {
            __syncthreads();
            if (tid == 0) {
                __threadfence();
                atomicAdd(&g_bar, 1u);
                const unsigned int target = (unsigned int)NBLK * (s + 1);
                while (*((volatile unsigned int*)&g_bar) < target) {
                    __nanosleep(64);
                }
                __threadfence();
            }
            __syncthreads();
        }
    }
}

// ---------------- emissions: feats = [h_f, h_b] @ W_h2t^T + b_h2t ---------
__global__ void feats_kernel(const float* __restrict__ Wh2t,
                             const float* __restrict__ bh2t) {
    extern __shared__ float Ws[];  // [23][1024]
    const int tid = threadIdx.x;
    for (int i = tid; i < KK * 1024; i += 256) Ws[i] = Wh2t[i];
    __syncthreads();

    const int w    = tid >> 5;
    const int lane = tid & 31;
    const int t    = blockIdx.x * 4 + (w >> 1);
    const int b    = (w & 1) * 32 + lane;

    float acc[KK];
#pragma unroll
    for (int k = 0; k < KK; k++) acc[k] = __ldg(bh2t + k);

    const float* __restrict__ hf = g_hs[0] + (size_t)t * HH * BB;
    for (int j = 0; j < HH; j++) {
        float hv = hf[j * BB + b];
#pragma unroll
        for (int k = 0; k < KK; k++)
            acc[k] = fmaf(hv, Ws[k * 1024 + j], acc[k]);
    }
    const float* __restrict__ hb = g_hs[1] + (size_t)t * HH * BB;
    for (int j = 0; j < HH; j++) {
        float hv = hb[j * BB + b];
#pragma unroll
        for (int k = 0; k < KK; k++)
            acc[k] = fmaf(hv, Ws[k * 1024 + HH + j], acc[k]);
    }
#pragma unroll
    for (int k = 0; k < KK; k++)
        g_feats[((size_t)b * TT + t) * KK + k] = acc[k];
}

// ---------------- Viterbi: one warp per batch element ---------------------
__global__ void viterbi_kernel(const float* __restrict__ trans,
                               const int* __restrict__ seq_len,
                               float* __restrict__ out) {
    const int b    = blockIdx.x;
    const int lane = threadIdx.x;
    __shared__ unsigned char bp[TT][24];

    const int L = seq_len[b];
    const bool active = lane < KK;

    float tr[KK];
#pragma unroll
    for (int p = 0; p < KK; p++)
        tr[p] = active ? trans[lane * KK + p] : -3.0e38f;

    float fv = (lane == START_TAG) ? 0.0f : NEGV;
    const float* __restrict__ fb = g_feats + (size_t)b * TT * KK;

    for (int t = 0; t < TT; t++) {
        float ft = active ? fb[t * KK + lane] : 0.0f;
        float best = -3.4e38f;
        int arg = 0;
#pragma unroll
        for (int p = 0; p < KK; p++) {
            float v = __shfl_sync(0xffffffffu, fv, p) + tr[p];
            if (v > best) { best = v; arg = p; }  // strict > => first max (jnp.argmax)
        }
        const bool m = (t < L);
        if (m) fv = best + ft;
        if (active) bp[t][lane] = m ? (unsigned char)arg : (unsigned char)lane;
    }

    float term = active ? (fv + trans[END_TAG * KK + lane]) : -3.4e38f;
    float bestv = -3.4e38f;
    int btag = 0;
#pragma unroll
    for (int p = 0; p < KK; p++) {
        float v = __shfl_sync(0xffffffffu, term, p);
        if (v > bestv) { bestv = v; btag = p; }
    }

    if (lane == 0) {
        out[b] = bestv;
        int tag = btag;
        out[BB + (size_t)b * TT + (TT - 1)] = (float)tag;
        for (int t = TT - 1; t >= 1; t--) {
            tag = bp[t][tag];
            out[BB + (size_t)b * TT + (t - 1)] = (float)tag;
        }
    }
}

// ---------------- launch -------------------------------------------------
extern "C" void kernel_launch(void* const* d_in, const int* in_sizes, int n_in,
                              void* d_out, int out_size) {
    const float* texts  = (const float*)d_in[0];
    const int*   seqlen = (const int*)d_in[1];
    const float* Wih_f  = (const float*)d_in[2];
    const float* Whh_f  = (const float*)d_in[3];
    const float* b_f    = (const float*)d_in[4];
    const float* Wih_b  = (const float*)d_in[5];
    const float* Whh_b  = (const float*)d_in[6];
    const float* b_b    = (const float*)d_in[7];
    const float* W_h2t  = (const float*)d_in[8];
    const float* b_h2t  = (const float*)d_in[9];
    const float* trans  = (const float*)d_in[10];
    float* out = (float*)d_out;

    cudaFuncSetAttribute(feats_kernel,
                         cudaFuncAttributeMaxDynamicSharedMemorySize, KK * 1024 * 4);

    init_kernel<<<32, 256>>>();
    xgemm_kernel<<<dim3(G4 / 128, (BB * TT) / 128, 2), 256>>>(texts, Wih_f, Wih_b, b_f, b_b);
    lstm_persistent<<<NBLK, 128>>>(Whh_f, Whh_b);
    feats_kernel<<<128, 256, KK * 1024 * 4>>>(W_h2t, b_h2t);
    viterbi_kernel<<<BB, 32>>>(trans, seqlen, out);
}

// round 3
// speedup vs baseline: 2.3249x; 1.1962x over previous
#include <cuda_runtime.h>
#include <math.h>

// Problem constants
#define BB 64      // batch
#define TT 512     // time
#define EE 512     // embed
#define HH 512     // hidden per direction
#define G4 2048    // 4*H
#define KK 23      // tags
#define START_TAG 1
#define END_TAG 2
#define NEGV -10000.0f
#define NBLK 128   // persistent grid size

typedef unsigned long long ull;

// ---------------- packed f32x2 helpers ----------------
__device__ __forceinline__ ull pack2(float lo, float hi) {
    ull r;
    asm("mov.b64 %0, {%1, %2};" : "=l"(r) : "f"(lo), "f"(hi));
    return r;
}
__device__ __forceinline__ void unpack2(ull v, float& lo, float& hi) {
    asm("mov.b64 {%0, %1}, %2;" : "=f"(lo), "=f"(hi) : "l"(v));
}
__device__ __forceinline__ void ffma2(ull& d, ull a, ull b) {
    asm("fma.rn.f32x2 %0, %1, %2, %3;" : "=l"(d) : "l"(a), "l"(b), "l"(d));
}

// ---------------- scratch (device globals; no allocation) ----------------
__device__ float g_xg[2][67108864];          // [dir][(b*T+t)*2048 + g*512 + u]
__device__ float g_hs[2][16777216];          // [dir][t*512*64 + u*64 + b]
__device__ float g_zero[HH * BB];            // stays zero (h_{-1})
__device__ float g_feats[BB * TT * KK];
__device__ unsigned int g_bar;

__global__ void init_kernel() {
    int idx = blockIdx.x * blockDim.x + threadIdx.x;
    for (int i = idx; i < HH * BB; i += gridDim.x * blockDim.x) g_zero[i] = 0.0f;
    if (idx == 0) g_bar = 0u;
}

// ---------------- input GEMM: C[m,n] = sum_k A[m,k]*W[n,k] + bias[n] ------
// A: [32768,512], W: [2048,512]. Tile 128x128xBK8, 256 thr, 8x8 micro via f32x2
__global__ __launch_bounds__(256, 2)
void xgemm_kernel(const float* __restrict__ A,
                  const float* __restrict__ Wf,
                  const float* __restrict__ Wb,
                  const float* __restrict__ bf,
                  const float* __restrict__ bb) {
    const int dir = blockIdx.z;
    const float* __restrict__ W = dir ? Wb : Wf;
    const float* __restrict__ bias = dir ? bb : bf;
    float* __restrict__ C = g_xg[dir];

    __shared__ __align__(16) float2 As2[8][128];  // duplicated A: 8KB
    __shared__ __align__(16) float  Bs[8][128];   // 4KB

    const int tid = threadIdx.x;
    const int m0 = blockIdx.y * 128;
    const int n0 = blockIdx.x * 128;
    const int lrow = tid >> 1;          // 0..127
    const int lkq  = (tid & 1) * 4;     // 0 or 4
    const int tx = (tid & 15) * 4;      // n frag base (also +64)
    const int ty = (tid >> 4) * 4;      // m frag base (also +64)

    ull acc2[8][4];
#pragma unroll
    for (int i = 0; i < 8; i++)
#pragma unroll
        for (int j = 0; j < 4; j++) acc2[i][j] = 0ull;

    for (int kt = 0; kt < EE; kt += 8) {
        float4 av = *(const float4*)(A + (size_t)(m0 + lrow) * EE + kt + lkq);
        float4 bv = *(const float4*)(W + (size_t)(n0 + lrow) * EE + kt + lkq);
        As2[lkq + 0][lrow] = make_float2(av.x, av.x);
        As2[lkq + 1][lrow] = make_float2(av.y, av.y);
        As2[lkq + 2][lrow] = make_float2(av.z, av.z);
        As2[lkq + 3][lrow] = make_float2(av.w, av.w);
        Bs[lkq + 0][lrow] = bv.x; Bs[lkq + 1][lrow] = bv.y;
        Bs[lkq + 2][lrow] = bv.z; Bs[lkq + 3][lrow] = bv.w;
        __syncthreads();
#pragma unroll
        for (int k = 0; k < 8; k++) {
            ull a[8], b[4];
            {
                ulonglong2 t0 = *(const ulonglong2*)&As2[k][ty];
                ulonglong2 t1 = *(const ulonglong2*)&As2[k][ty + 2];
                ulonglong2 t2 = *(const ulonglong2*)&As2[k][ty + 64];
                ulonglong2 t3 = *(const ulonglong2*)&As2[k][ty + 66];
                a[0] = t0.x; a[1] = t0.y; a[2] = t1.x; a[3] = t1.y;
                a[4] = t2.x; a[5] = t2.y; a[6] = t3.x; a[7] = t3.y;
                ulonglong2 u0 = *(const ulonglong2*)&Bs[k][tx];
                ulonglong2 u1 = *(const ulonglong2*)&Bs[k][tx + 64];
                b[0] = u0.x; b[1] = u0.y; b[2] = u1.x; b[3] = u1.y;
            }
#pragma unroll
            for (int i = 0; i < 8; i++)
#pragma unroll
                for (int j = 0; j < 4; j++)
                    ffma2(acc2[i][j], a[i], b[j]);
        }
        __syncthreads();
    }
    // epilogue + bias
    float4 bia0 = *(const float4*)(bias + n0 + tx);
    float4 bia1 = *(const float4*)(bias + n0 + tx + 64);
#pragma unroll
    for (int i = 0; i < 8; i++) {
        int m = m0 + ((i < 4) ? (ty + i) : (ty + 64 + i - 4));
        float l0, h0, l1, h1, l2, h2, l3, h3;
        unpack2(acc2[i][0], l0, h0);
        unpack2(acc2[i][1], l1, h1);
        unpack2(acc2[i][2], l2, h2);
        unpack2(acc2[i][3], l3, h3);
        float4 o0, o1;
        o0.x = l0 + bia0.x; o0.y = h0 + bia0.y;
        o0.z = l1 + bia0.z; o0.w = h1 + bia0.w;
        o1.x = l2 + bia1.x; o1.y = h2 + bia1.y;
        o1.z = l3 + bia1.z; o1.w = h3 + bia1.w;
        *(float4*)(C + (size_t)m * G4 + n0 + tx)      = o0;
        *(float4*)(C + (size_t)m * G4 + n0 + tx + 64) = o1;
    }
}

// ---------------- persistent bidirectional LSTM ---------------------------
// 128 blocks x 256 threads. block: dir = blk>>6, 8 units (ublk*8 + warp).
// warp = one unit; lane -> batches (b0=2*lane, b0+1) packed in f32x2.
// Whh slice duplicated in smem (128KB); h staged per 128-k chunk (2x32KB).
__device__ __forceinline__ float sigf(float x) {
    return 1.0f / (1.0f + __expf(-x));
}
__device__ __forceinline__ float tanhfast(float x) {
    return 1.0f - 2.0f / (__expf(2.0f * x) + 1.0f);
}

__global__ __launch_bounds__(256, 1)
void lstm_persistent(const float* __restrict__ Whh_f,
                     const float* __restrict__ Whh_b) {
    const int blk  = blockIdx.x;
    const int dir  = blk >> 6;
    const int ublk = blk & 63;
    const float* __restrict__ Whh = dir ? Whh_b : Whh_f;

    extern __shared__ __align__(16) char sm[];
    float2* __restrict__ w2 = (float2*)sm;              // [8][4][512] 128KB
    float*  __restrict__ hb = (float*)(sm + 131072);    // [2][8192]   64KB

    const int tid  = threadIdx.x;
    const int warp = tid >> 5;
    const int lane = tid & 31;

    // load + duplicate weight slice once: w2[u][g][k] = (w,w)
    for (int idx = tid; idx < 8 * 4 * HH; idx += 256) {
        int u = idx >> 11;
        int g = (idx >> 9) & 3;
        int k = idx & 511;
        float v = Whh[(size_t)(g * HH + ublk * 8 + u) * HH + k];
        w2[((u << 2) + g) * HH + k] = make_float2(v, v);
    }
    __syncthreads();

    const int u_glob = ublk * 8 + warp;
    const int b0 = lane * 2;
    const float* __restrict__ xg = g_xg[dir];
    float* __restrict__ hs_base = g_hs[dir];
    const float2* __restrict__ wgi = w2 + ((warp << 2) + 0) * HH;
    const float2* __restrict__ wgf = w2 + ((warp << 2) + 1) * HH;
    const float2* __restrict__ wgg = w2 + ((warp << 2) + 2) * HH;
    const float2* __restrict__ wgo = w2 + ((warp << 2) + 3) * HH;

    float c0 = 0.0f, c1 = 0.0f;

    for (int s = 0; s < TT; s++) {
        const int t = dir ? (TT - 1 - s) : s;
        const float4* __restrict__ hp4 = (const float4*)
            ((s == 0) ? g_zero : (hs_base + (size_t)(dir ? t + 1 : t - 1) * HH * BB));

        // input-projection gates (independent of h; issue early)
        const size_t xb0 = ((size_t)b0 * TT + t) * G4 + u_glob;
        const size_t xb1 = xb0 + (size_t)TT * G4;
        const float xi0 = xg[xb0];            const float xi1 = xg[xb1];
        const float xf0 = xg[xb0 + HH];       const float xf1 = xg[xb1 + HH];
        const float xgg0 = xg[xb0 + 2 * HH];  const float xgg1 = xg[xb1 + 2 * HH];
        const float xo0 = xg[xb0 + 3 * HH];   const float xo1 = xg[xb1 + 3 * HH];

        // stage chunk 0 into buffer 0
        {
            float4* dst = (float4*)hb;
#pragma unroll
            for (int j = 0; j < 8; j++)
                dst[j * 256 + tid] = hp4[j * 256 + tid];
        }

        ull ai = 0ull, af = 0ull, ag = 0ull, ao = 0ull;

#pragma unroll
        for (int c = 0; c < 4; c++) {
            __syncthreads();   // buffer (c&1) ready
            float4 pf[8];
            if (c < 3) {
#pragma unroll
                for (int j = 0; j < 8; j++)
                    pf[j] = hp4[(c + 1) * 2048 + j * 256 + tid];
            }
            const float* __restrict__ hc = hb + (c & 1) * 8192;
#pragma unroll 4
            for (int kk = 0; kk < 128; kk += 2) {
                const int k = c * 128 + kk;
                ulonglong2 wi = *(const ulonglong2*)(wgi + k);
                ulonglong2 wf = *(const ulonglong2*)(wgf + k);
                ulonglong2 wg = *(const ulonglong2*)(wgg + k);
                ulonglong2 wo = *(const ulonglong2*)(wgo + k);
                ull h0 = *(const ull*)(hc + (kk + 0) * BB + b0);
                ull h1 = *(const ull*)(hc + (kk + 1) * BB + b0);
                ffma2(ai, wi.x, h0); ffma2(ai, wi.y, h1);
                ffma2(af, wf.x, h0); ffma2(af, wf.y, h1);
                ffma2(ag, wg.x, h0); ffma2(ag, wg.y, h1);
                ffma2(ao, wo.x, h0); ffma2(ao, wo.y, h1);
            }
            if (c < 3) {
                float4* dst = (float4*)(hb + ((c + 1) & 1) * 8192);
#pragma unroll
                for (int j = 0; j < 8; j++)
                    dst[j * 256 + tid] = pf[j];
            }
        }

        float ai0, ai1, af0, af1, ag0, ag1, ao0, ao1;
        unpack2(ai, ai0, ai1); unpack2(af, af0, af1);
        unpack2(ag, ag0, ag1); unpack2(ao, ao0, ao1);
        ai0 += xi0; ai1 += xi1; af0 += xf0; af1 += xf1;
        ag0 += xgg0; ag1 += xgg1; ao0 += xo0; ao1 += xo1;

        const float i0 = sigf(ai0), f0 = sigf(af0), gg0 = tanhfast(ag0), o0 = sigf(ao0);
        const float i1 = sigf(ai1), f1 = sigf(af1), gg1 = tanhfast(ag1), o1 = sigf(ao1);
        c0 = f0 * c0 + i0 * gg0;
        c1 = f1 * c1 + i1 * gg1;
        float2 hv;
        hv.x = o0 * tanhfast(c0);
        hv.y = o1 * tanhfast(c1);
        *(float2*)&hs_base[(size_t)t * HH * BB + u_glob * BB + b0] = hv;

        // global barrier (skip after last step)
        if (s != TT - 1) {
            __syncthreads();
            if (tid == 0) {
                __threadfence();
                atomicAdd(&g_bar, 1u);
                const unsigned int target = (unsigned int)NBLK * (s + 1);
                while (*((volatile unsigned int*)&g_bar) < target) {
                    __nanosleep(32);
                }
                __threadfence();
            }
            __syncthreads();
        }
    }
}

// ---------------- emissions: feats = [h_f, h_b] @ W_h2t^T + b_h2t ---------
// grid 256 blocks x 128 thr: block covers 2 t x 64 b
__global__ __launch_bounds__(128, 2)
void feats_kernel(const float* __restrict__ Wh2t,
                  const float* __restrict__ bh2t) {
    extern __shared__ float Ws[];  // [23][1024]
    const int tid = threadIdx.x;
    for (int i = tid; i < KK * 1024; i += 128) Ws[i] = Wh2t[i];
    __syncthreads();

    const int w    = tid >> 5;
    const int lane = tid & 31;
    const int t    = blockIdx.x * 2 + (w >> 1);
    const int b    = (w & 1) * 32 + lane;

    float acc[KK];
#pragma unroll
    for (int k = 0; k < KK; k++) acc[k] = __ldg(bh2t + k);

    const float* __restrict__ hf = g_hs[0] + (size_t)t * HH * BB;
    for (int j = 0; j < HH; j++) {
        float hv = hf[j * BB + b];
#pragma unroll
        for (int k = 0; k < KK; k++)
            acc[k] = fmaf(hv, Ws[k * 1024 + j], acc[k]);
    }
    const float* __restrict__ hbv = g_hs[1] + (size_t)t * HH * BB;
    for (int j = 0; j < HH; j++) {
        float hv = hbv[j * BB + b];
#pragma unroll
        for (int k = 0; k < KK; k++)
            acc[k] = fmaf(hv, Ws[k * 1024 + HH + j], acc[k]);
    }
#pragma unroll
    for (int k = 0; k < KK; k++)
        g_feats[((size_t)b * TT + t) * KK + k] = acc[k];
}

// ---------------- Viterbi: one warp per batch element ---------------------
__global__ void viterbi_kernel(const float* __restrict__ trans,
                               const int* __restrict__ seq_len,
                               float* __restrict__ out) {
    const int b    = blockIdx.x;
    const int lane = threadIdx.x;
    __shared__ unsigned char bp[TT][24];

    const int L = seq_len[b];
    const bool active = lane < KK;

    float tr[KK];
#pragma unroll
    for (int p = 0; p < KK; p++)
        tr[p] = active ? trans[lane * KK + p] : -3.0e38f;

    float fv = (lane == START_TAG) ? 0.0f : NEGV;
    const float* __restrict__ fb = g_feats + (size_t)b * TT * KK;

    for (int t = 0; t < TT; t++) {
        float ft = active ? fb[t * KK + lane] : 0.0f;
        float best = -3.4e38f;
        int arg = 0;
#pragma unroll
        for (int p = 0; p < KK; p++) {
            float v = __shfl_sync(0xffffffffu, fv, p) + tr[p];
            if (v > best) { best = v; arg = p; }  // strict > => first max (jnp.argmax)
        }
        const bool m = (t < L);
        if (m) fv = best + ft;
        if (active) bp[t][lane] = m ? (unsigned char)arg : (unsigned char)lane;
    }

    float term = active ? (fv + trans[END_TAG * KK + lane]) : -3.4e38f;
    float bestv = -3.4e38f;
    int btag = 0;
#pragma unroll
    for (int p = 0; p < KK; p++) {
        float v = __shfl_sync(0xffffffffu, term, p);
        if (v > bestv) { bestv = v; btag = p; }
    }

    if (lane == 0) {
        out[b] = bestv;
        int tag = btag;
        out[BB + (size_t)b * TT + (TT - 1)] = (float)tag;
        for (int t = TT - 1; t >= 1; t--) {
            tag = bp[t][tag];
            out[BB + (size_t)b * TT + (t - 1)] = (float)tag;
        }
    }
}

// ---------------- launch -------------------------------------------------
extern "C" void kernel_launch(void* const* d_in, const int* in_sizes, int n_in,
                              void* d_out, int out_size) {
    const float* texts  = (const float*)d_in[0];
    const int*   seqlen = (const int*)d_in[1];
    const float* Wih_f  = (const float*)d_in[2];
    const float* Whh_f  = (const float*)d_in[3];
    const float* b_f    = (const float*)d_in[4];
    const float* Wih_b  = (const float*)d_in[5];
    const float* Whh_b  = (const float*)d_in[6];
    const float* b_b    = (const float*)d_in[7];
    const float* W_h2t  = (const float*)d_in[8];
    const float* b_h2t  = (const float*)d_in[9];
    const float* trans  = (const float*)d_in[10];
    float* out = (float*)d_out;

    cudaFuncSetAttribute(lstm_persistent,
                         cudaFuncAttributeMaxDynamicSharedMemorySize, 196608);
    cudaFuncSetAttribute(feats_kernel,
                         cudaFuncAttributeMaxDynamicSharedMemorySize, KK * 1024 * 4);

    init_kernel<<<32, 256>>>();
    xgemm_kernel<<<dim3(G4 / 128, (BB * TT) / 128, 2), 256>>>(texts, Wih_f, Wih_b, b_f, b_b);
    lstm_persistent<<<NBLK, 256, 196608>>>(Whh_f, Whh_b);
    feats_kernel<<<256, 128, KK * 1024 * 4>>>(W_h2t, b_h2t);
    viterbi_kernel<<<BB, 32>>>(trans, seqlen, out);
}